// round 2
// baseline (speedup 1.0000x reference)
#include <cuda_runtime.h>

#define DT 0.025f

__global__ void __launch_bounds__(256)
get_next_states_kernel(const float* __restrict__ params,
                       const float* __restrict__ states,
                       const float* __restrict__ actions,
                       const float* __restrict__ foot_pos,
                       const int* __restrict__ foot_contacts,
                       float* __restrict__ out,
                       int n)
{
    int i = blockIdx.x * blockDim.x + threadIdx.x;
    if (i >= n) return;

    // ---- per-kernel constants from params (broadcast L1 hits) ----
    float p0 = __ldg(params + 0);
    float p1 = __ldg(params + 1);
    float p2 = __ldg(params + 2);
    float p3 = __ldg(params + 3);
    float p4 = __ldg(params + 4);
    float p5 = __ldg(params + 5);
    float p6 = __ldg(params + 6);

    float inv_mass = 1.0f / p0;

    // inertia = L L^T + 1e-5 (scalar broadcast add to ALL entries)
    float I00 = p1*p1 + 1e-5f;
    float I01 = p1*p2 + 1e-5f;
    float I02 = p1*p4 + 1e-5f;
    float I11 = p2*p2 + p3*p3 + 1e-5f;
    float I12 = p2*p4 + p3*p5 + 1e-5f;
    float I22 = p4*p4 + p5*p5 + p6*p6 + 1e-5f;

    // symmetric 3x3 inverse via adjugate
    float c00 = I11*I22 - I12*I12;
    float c01 = I02*I12 - I01*I22;
    float c02 = I01*I12 - I02*I11;
    float det = I00*c00 + I01*c01 + I02*c02;
    float invdet = 1.0f / det;
    float iI00 = c00 * invdet;
    float iI01 = c01 * invdet;
    float iI02 = c02 * invdet;
    float iI11 = (I00*I22 - I02*I02) * invdet;
    float iI12 = (I02*I01 - I00*I12) * invdet;
    float iI22 = (I00*I11 - I01*I01) * invdet;

    // ---- per-row state loads (13 floats, stride 13 -> fully dense sectors) ----
    const float* s = states + (long)i * 13;
    float s0 = s[0],  s1 = s[1],  s2 = s[2],  s3 = s[3],  s4 = s[4];
    float s5 = s[5],  s6 = s[6],  s7 = s[7],  s8 = s[8],  s9 = s[9];
    float s10 = s[10], s11 = s[11], s12 = s[12];

    float sr, cr, sp, cp, sy, cy;
    sincosf(s0, &sr, &cr);
    sincosf(s1, &sp, &cp);
    sincosf(s2, &sy, &cy);

    // rotation matrix (ZYX)
    float R00 = cy*cp, R01 = cy*sp*sr - sy*cr, R02 = cy*sp*cr + sy*sr;
    float R10 = sy*cp, R11 = sy*sp*sr + cy*cr, R12 = sy*sp*cr - cy*sr;
    float R20 = -sp,   R21 = cp*sr,            R22 = cp*cr;

    float rcp_cp = 1.0f / cp;

    // ---- vectorized action / foot-position loads (48B rows, 16B aligned) ----
    const float4* a4 = (const float4*)(actions  + (long)i * 12);
    const float4* f4 = (const float4*)(foot_pos + (long)i * 12);
    float4 aA = a4[0], aB = a4[1], aC = a4[2];
    float4 fA = f4[0], fB = f4[1], fC = f4[2];

    float ax[4] = { aA.x, aA.w, aB.z, aC.y };
    float ay[4] = { aA.y, aB.x, aB.w, aC.z };
    float az[4] = { aA.z, aB.y, aC.x, aC.w };
    float px[4] = { fA.x, fA.w, fB.z, fC.y };
    float py[4] = { fA.y, fB.x, fB.w, fC.z };
    float pz[4] = { fA.z, fB.y, fC.x, fC.w };

    // contacts marshaled as 4-byte elements (int32 0/1 or float32 0.0/1.0);
    // raw-bits != 0 test is correct for both.
    int4 fc4 = *(const int4*)(foot_contacts + (long)i * 4);
    float fcw[4] = { (float)(fc4.x != 0), (float)(fc4.y != 0),
                     (float)(fc4.z != 0), (float)(fc4.w != 0) };

    // accumulate w = sum_f fc * (foot_world_f x a_f) and F = sum_f fc * a_f
    float wx = 0.f, wy = 0.f, wz = 0.f;
    float Fx = 0.f, Fy = 0.f, Fz = 0.f;
    #pragma unroll
    for (int f = 0; f < 4; f++) {
        float vx = R00*px[f] + R01*py[f] + R02*pz[f];
        float vy = R10*px[f] + R11*py[f] + R12*pz[f];
        float vz = R20*px[f] + R21*py[f] + R22*pz[f];
        float cxs = vy*az[f] - vz*ay[f];
        float cys = vz*ax[f] - vx*az[f];
        float czs = vx*ay[f] - vy*ax[f];
        wx += fcw[f] * cxs;
        wy += fcw[f] * cys;
        wz += fcw[f] * czs;
        Fx += fcw[f] * ax[f];
        Fy += fcw[f] * ay[f];
        Fz += fcw[f] * az[f];
    }

    // t = R * invI * R^T * w  (inv_inertia_world applied without forming it)
    float ux = R00*wx + R10*wy + R20*wz;
    float uy = R01*wx + R11*wy + R21*wz;
    float uz = R02*wx + R12*wy + R22*wz;
    float vx = iI00*ux + iI01*uy + iI02*uz;
    float vy = iI01*ux + iI11*uy + iI12*uz;
    float vz = iI02*ux + iI12*uy + iI22*uz;
    float tx = R00*vx + R01*vy + R02*vz;
    float ty = R10*vx + R11*vy + R12*vz;
    float tz = R20*vx + R21*vy + R22*vz;

    // ---- outputs: out = A@s + B@a collapsed to scalar equations ----
    float* o = out + (long)i * 13;
    float m0 = cy*s6 + sy*s7;                 // shared by rows 0 and 2
    o[0]  = s0 + DT * (m0 * rcp_cp);
    o[1]  = s1 + DT * (cy*s7 - sy*s6);
    o[2]  = s2 + DT * (m0 * sp * rcp_cp + s8);
    o[3]  = s3 + DT * s9;
    o[4]  = s4 + DT * s10;
    o[5]  = s5 + DT * s11;
    o[6]  = s6 + DT * tx;
    o[7]  = s7 + DT * ty;
    o[8]  = s8 + DT * tz;
    o[9]  = s9  + DT * inv_mass * Fx;
    o[10] = s10 + DT * inv_mass * Fy;
    o[11] = s11 + DT * (inv_mass * Fz + s12);
    o[12] = s12;
}

extern "C" void kernel_launch(void* const* d_in, const int* in_sizes, int n_in,
                              void* d_out, int out_size) {
    const float* params   = (const float*)d_in[0];
    const float* states   = (const float*)d_in[1];
    const float* actions  = (const float*)d_in[2];
    const float* foot_pos = (const float*)d_in[3];
    const int*   foot_contacts = (const int*)d_in[4];
    float* out = (float*)d_out;

    int n = in_sizes[1] / 13;  // batch size from states element count
    int threads = 256;
    int blocks = (n + threads - 1) / threads;
    get_next_states_kernel<<<blocks, threads>>>(params, states, actions,
                                                foot_pos, foot_contacts, out, n);
}

// round 3
// speedup vs baseline: 1.5783x; 1.5783x over previous
#include <cuda_runtime.h>

#define DT 0.025f
#define NTHREADS 256
#define ROW 13
#define BLK_FLOATS (NTHREADS * ROW)          // 3328
#define BLK_VEC4   (BLK_FLOATS / 4)          // 832

__global__ void __launch_bounds__(NTHREADS)
get_next_states_kernel(const float* __restrict__ params,
                       const float* __restrict__ states,
                       const float* __restrict__ actions,
                       const float* __restrict__ foot_pos,
                       const int* __restrict__ foot_contacts,
                       float* __restrict__ out,
                       int n)
{
    __shared__ float sbuf[BLK_FLOATS];

    int tid = threadIdx.x;
    int blockBase = blockIdx.x * NTHREADS;
    int i = blockBase + tid;
    bool fullBlock = (blockBase + NTHREADS) <= n;

    // ---- per-kernel constants from params (broadcast L1 hits) ----
    float p0 = __ldg(params + 0);
    float p1 = __ldg(params + 1);
    float p2 = __ldg(params + 2);
    float p3 = __ldg(params + 3);
    float p4 = __ldg(params + 4);
    float p5 = __ldg(params + 5);
    float p6 = __ldg(params + 6);

    // ---- issue independent per-row loads early (overlap with staging) ----
    float4 aA, aB, aC, fA, fB, fC;
    int4 fc4 = make_int4(0, 0, 0, 0);
    if (i < n) {
        const float4* a4 = (const float4*)(actions  + (size_t)i * 12);
        const float4* f4 = (const float4*)(foot_pos + (size_t)i * 12);
        aA = a4[0]; aB = a4[1]; aC = a4[2];
        fA = f4[0]; fB = f4[1]; fC = f4[2];
        fc4 = *(const int4*)(foot_contacts + (size_t)i * 4);
    } else {
        aA = aB = aC = fA = fB = fC = make_float4(0.f, 0.f, 0.f, 0.f);
    }

    // ---- cooperative coalesced stage of states into smem ----
    if (fullBlock) {
        const float4* src = (const float4*)(states + (size_t)blockBase * ROW);
        float4* dst = (float4*)sbuf;
        #pragma unroll
        for (int j = 0; j < 4; j++) {
            int idx = tid + j * NTHREADS;
            if (idx < BLK_VEC4) dst[idx] = src[idx];
        }
    } else {
        int lim = (n - blockBase) * ROW;
        const float* src = states + (size_t)blockBase * ROW;
        for (int j = tid; j < lim; j += NTHREADS) sbuf[j] = src[j];
    }
    __syncthreads();

    // ---- per-row state reads from smem (stride 13: bank-conflict-free) ----
    const float* s = sbuf + tid * ROW;
    float s0 = s[0],  s1 = s[1],  s2 = s[2],  s3 = s[3],  s4 = s[4];
    float s5 = s[5],  s6 = s[6],  s7 = s[7],  s8 = s[8],  s9 = s[9];
    float s10 = s[10], s11 = s[11], s12 = s[12];

    // ---- constants: inertia inverse (recomputed per thread, ALU-cheap) ----
    float inv_mass = 1.0f / p0;
    float I00 = p1*p1 + 1e-5f;
    float I01 = p1*p2 + 1e-5f;
    float I02 = p1*p4 + 1e-5f;
    float I11 = p2*p2 + p3*p3 + 1e-5f;
    float I12 = p2*p4 + p3*p5 + 1e-5f;
    float I22 = p4*p4 + p5*p5 + p6*p6 + 1e-5f;
    float c00 = I11*I22 - I12*I12;
    float c01 = I02*I12 - I01*I22;
    float c02 = I01*I12 - I02*I11;
    float det = I00*c00 + I01*c01 + I02*c02;
    float invdet = 1.0f / det;
    float iI00 = c00 * invdet;
    float iI01 = c01 * invdet;
    float iI02 = c02 * invdet;
    float iI11 = (I00*I22 - I02*I02) * invdet;
    float iI12 = (I02*I01 - I00*I12) * invdet;
    float iI22 = (I00*I11 - I01*I01) * invdet;

    float sr, cr, sp, cp, sy, cy;
    sincosf(s0, &sr, &cr);
    sincosf(s1, &sp, &cp);
    sincosf(s2, &sy, &cy);

    float R00 = cy*cp, R01 = cy*sp*sr - sy*cr, R02 = cy*sp*cr + sy*sr;
    float R10 = sy*cp, R11 = sy*sp*sr + cy*cr, R12 = sy*sp*cr - cy*sr;
    float R20 = -sp,   R21 = cp*sr,            R22 = cp*cr;
    float rcp_cp = 1.0f / cp;

    float ax[4] = { aA.x, aA.w, aB.z, aC.y };
    float ay[4] = { aA.y, aB.x, aB.w, aC.z };
    float az[4] = { aA.z, aB.y, aC.x, aC.w };
    float px[4] = { fA.x, fA.w, fB.z, fC.y };
    float py[4] = { fA.y, fB.x, fB.w, fC.z };
    float pz[4] = { fA.z, fB.y, fC.x, fC.w };
    float fcw[4] = { (float)(fc4.x != 0), (float)(fc4.y != 0),
                     (float)(fc4.z != 0), (float)(fc4.w != 0) };

    // w = sum_f fc * (foot_world_f x a_f); F = sum_f fc * a_f
    float wx = 0.f, wy = 0.f, wz = 0.f;
    float Fx = 0.f, Fy = 0.f, Fz = 0.f;
    #pragma unroll
    for (int f = 0; f < 4; f++) {
        float vx = R00*px[f] + R01*py[f] + R02*pz[f];
        float vy = R10*px[f] + R11*py[f] + R12*pz[f];
        float vz = R20*px[f] + R21*py[f] + R22*pz[f];
        wx += fcw[f] * (vy*az[f] - vz*ay[f]);
        wy += fcw[f] * (vz*ax[f] - vx*az[f]);
        wz += fcw[f] * (vx*ay[f] - vy*ax[f]);
        Fx += fcw[f] * ax[f];
        Fy += fcw[f] * ay[f];
        Fz += fcw[f] * az[f];
    }

    // t = R * invI * R^T * w
    float ux = R00*wx + R10*wy + R20*wz;
    float uy = R01*wx + R11*wy + R21*wz;
    float uz = R02*wx + R12*wy + R22*wz;
    float vx = iI00*ux + iI01*uy + iI02*uz;
    float vy = iI01*ux + iI11*uy + iI12*uz;
    float vz = iI02*ux + iI12*uy + iI22*uz;
    float tx = R00*vx + R01*vy + R02*vz;
    float ty = R10*vx + R11*vy + R12*vz;
    float tz = R20*vx + R21*vy + R22*vz;

    float m0 = cy*s6 + sy*s7;
    float o0  = s0 + DT * (m0 * rcp_cp);
    float o1  = s1 + DT * (cy*s7 - sy*s6);
    float o2  = s2 + DT * (m0 * sp * rcp_cp + s8);
    float o3  = s3 + DT * s9;
    float o4  = s4 + DT * s10;
    float o5  = s5 + DT * s11;
    float o6  = s6 + DT * tx;
    float o7  = s7 + DT * ty;
    float o8  = s8 + DT * tz;
    float o9  = s9  + DT * inv_mass * Fx;
    float o10 = s10 + DT * inv_mass * Fy;
    float o11 = s11 + DT * (inv_mass * Fz + s12);
    float o12 = s12;

    // ---- stage results and cooperatively store coalesced float4 ----
    __syncthreads();             // all smem reads done before overwrite
    float* w13 = sbuf + tid * ROW;
    w13[0] = o0;  w13[1] = o1;  w13[2] = o2;  w13[3] = o3;  w13[4] = o4;
    w13[5] = o5;  w13[6] = o6;  w13[7] = o7;  w13[8] = o8;  w13[9] = o9;
    w13[10] = o10; w13[11] = o11; w13[12] = o12;
    __syncthreads();

    if (fullBlock) {
        float4* dst = (float4*)(out + (size_t)blockBase * ROW);
        const float4* src = (const float4*)sbuf;
        #pragma unroll
        for (int j = 0; j < 4; j++) {
            int idx = tid + j * NTHREADS;
            if (idx < BLK_VEC4) dst[idx] = src[idx];
        }
    } else {
        int lim = (n - blockBase) * ROW;
        float* dst = out + (size_t)blockBase * ROW;
        for (int j = tid; j < lim; j += NTHREADS) dst[j] = sbuf[j];
    }
}

extern "C" void kernel_launch(void* const* d_in, const int* in_sizes, int n_in,
                              void* d_out, int out_size) {
    const float* params   = (const float*)d_in[0];
    const float* states   = (const float*)d_in[1];
    const float* actions  = (const float*)d_in[2];
    const float* foot_pos = (const float*)d_in[3];
    const int*   foot_contacts = (const int*)d_in[4];
    float* out = (float*)d_out;

    int n = in_sizes[1] / 13;
    int blocks = (n + NTHREADS - 1) / NTHREADS;
    get_next_states_kernel<<<blocks, NTHREADS>>>(params, states, actions,
                                                 foot_pos, foot_contacts, out, n);
}

// round 4
// speedup vs baseline: 1.6416x; 1.0401x over previous
#include <cuda_runtime.h>

#define DT 0.025f
#define NTHREADS 128
#define ROW 13
#define BLK_FLOATS (NTHREADS * ROW)          // 1664
#define BLK_VEC4   (BLK_FLOATS / 4)          // 416

__global__ void __launch_bounds__(NTHREADS, 6)
get_next_states_kernel(const float* __restrict__ params,
                       const float* __restrict__ states,
                       const float* __restrict__ actions,
                       const float* __restrict__ foot_pos,
                       const int* __restrict__ foot_contacts,
                       float* __restrict__ out,
                       int n)
{
    __shared__ float sin[BLK_FLOATS];
    __shared__ float sout[BLK_FLOATS];

    int tid = threadIdx.x;
    int blockBase = blockIdx.x * NTHREADS;
    int i = blockBase + tid;
    bool fullBlock = (blockBase + NTHREADS) <= n;

    // ---- per-kernel constants from params (broadcast L1 hits) ----
    float p0 = __ldg(params + 0);
    float p1 = __ldg(params + 1);
    float p2 = __ldg(params + 2);
    float p3 = __ldg(params + 3);
    float p4 = __ldg(params + 4);
    float p5 = __ldg(params + 5);
    float p6 = __ldg(params + 6);

    // ---- issue independent per-row loads early (overlap with staging) ----
    float4 aA, aB, aC, fA, fB, fC;
    int4 fc4 = make_int4(0, 0, 0, 0);
    if (i < n) {
        const float4* a4 = (const float4*)(actions  + (size_t)i * 12);
        const float4* f4 = (const float4*)(foot_pos + (size_t)i * 12);
        aA = a4[0]; aB = a4[1]; aC = a4[2];
        fA = f4[0]; fB = f4[1]; fC = f4[2];
        fc4 = *(const int4*)(foot_contacts + (size_t)i * 4);
    } else {
        aA = aB = aC = fA = fB = fC = make_float4(0.f, 0.f, 0.f, 0.f);
    }

    // ---- cooperative coalesced stage of states into smem ----
    if (fullBlock) {
        const float4* src = (const float4*)(states + (size_t)blockBase * ROW);
        float4* dst = (float4*)sin;
        #pragma unroll
        for (int j = 0; j < 4; j++) {
            int idx = tid + j * NTHREADS;
            if (idx < BLK_VEC4) dst[idx] = src[idx];
        }
    } else {
        int lim = (n - blockBase) * ROW;
        const float* src = states + (size_t)blockBase * ROW;
        for (int j = tid; j < lim; j += NTHREADS) sin[j] = src[j];
    }
    __syncthreads();

    // ---- per-row state reads from smem (stride 13: bank-conflict-free) ----
    const float* s = sin + tid * ROW;
    float s0 = s[0],  s1 = s[1],  s2 = s[2],  s3 = s[3],  s4 = s[4];
    float s5 = s[5],  s6 = s[6],  s7 = s[7],  s8 = s[8],  s9 = s[9];
    float s10 = s[10], s11 = s[11], s12 = s[12];

    // ---- constants: inertia inverse (recomputed per thread, ALU-cheap) ----
    float inv_mass = 1.0f / p0;
    float I00 = p1*p1 + 1e-5f;
    float I01 = p1*p2 + 1e-5f;
    float I02 = p1*p4 + 1e-5f;
    float I11 = p2*p2 + p3*p3 + 1e-5f;
    float I12 = p2*p4 + p3*p5 + 1e-5f;
    float I22 = p4*p4 + p5*p5 + p6*p6 + 1e-5f;
    float c00 = I11*I22 - I12*I12;
    float c01 = I02*I12 - I01*I22;
    float c02 = I01*I12 - I02*I11;
    float det = I00*c00 + I01*c01 + I02*c02;
    float invdet = 1.0f / det;
    float iI00 = c00 * invdet;
    float iI01 = c01 * invdet;
    float iI02 = c02 * invdet;
    float iI11 = (I00*I22 - I02*I02) * invdet;
    float iI12 = (I02*I01 - I00*I12) * invdet;
    float iI22 = (I00*I11 - I01*I01) * invdet;

    float sr, cr, sp, cp, sy, cy;
    sincosf(s0, &sr, &cr);
    sincosf(s1, &sp, &cp);
    sincosf(s2, &sy, &cy);

    float R00 = cy*cp, R01 = cy*sp*sr - sy*cr, R02 = cy*sp*cr + sy*sr;
    float R10 = sy*cp, R11 = sy*sp*sr + cy*cr, R12 = sy*sp*cr - cy*sr;
    float R20 = -sp,   R21 = cp*sr,            R22 = cp*cr;
    float rcp_cp = 1.0f / cp;

    float ax[4] = { aA.x, aA.w, aB.z, aC.y };
    float ay[4] = { aA.y, aB.x, aB.w, aC.z };
    float az[4] = { aA.z, aB.y, aC.x, aC.w };
    float px[4] = { fA.x, fA.w, fB.z, fC.y };
    float py[4] = { fA.y, fB.x, fB.w, fC.z };
    float pz[4] = { fA.z, fB.y, fC.x, fC.w };
    float fcw[4] = { (float)(fc4.x != 0), (float)(fc4.y != 0),
                     (float)(fc4.z != 0), (float)(fc4.w != 0) };

    // w = sum_f fc * (foot_world_f x a_f); F = sum_f fc * a_f
    float wx = 0.f, wy = 0.f, wz = 0.f;
    float Fx = 0.f, Fy = 0.f, Fz = 0.f;
    #pragma unroll
    for (int f = 0; f < 4; f++) {
        float vx = R00*px[f] + R01*py[f] + R02*pz[f];
        float vy = R10*px[f] + R11*py[f] + R12*pz[f];
        float vz = R20*px[f] + R21*py[f] + R22*pz[f];
        wx += fcw[f] * (vy*az[f] - vz*ay[f]);
        wy += fcw[f] * (vz*ax[f] - vx*az[f]);
        wz += fcw[f] * (vx*ay[f] - vy*ax[f]);
        Fx += fcw[f] * ax[f];
        Fy += fcw[f] * ay[f];
        Fz += fcw[f] * az[f];
    }

    // t = R * invI * R^T * w
    float ux = R00*wx + R10*wy + R20*wz;
    float uy = R01*wx + R11*wy + R21*wz;
    float uz = R02*wx + R12*wy + R22*wz;
    float vx = iI00*ux + iI01*uy + iI02*uz;
    float vy = iI01*ux + iI11*uy + iI12*uz;
    float vz = iI02*ux + iI12*uy + iI22*uz;
    float tx = R00*vx + R01*vy + R02*vz;
    float ty = R10*vx + R11*vy + R12*vz;
    float tz = R20*vx + R21*vy + R22*vz;

    float m0 = cy*s6 + sy*s7;

    // ---- write results to the separate output staging buffer ----
    float* w13 = sout + tid * ROW;
    w13[0]  = s0 + DT * (m0 * rcp_cp);
    w13[1]  = s1 + DT * (cy*s7 - sy*s6);
    w13[2]  = s2 + DT * (m0 * sp * rcp_cp + s8);
    w13[3]  = s3 + DT * s9;
    w13[4]  = s4 + DT * s10;
    w13[5]  = s5 + DT * s11;
    w13[6]  = s6 + DT * tx;
    w13[7]  = s7 + DT * ty;
    w13[8]  = s8 + DT * tz;
    w13[9]  = s9  + DT * inv_mass * Fx;
    w13[10] = s10 + DT * inv_mass * Fy;
    w13[11] = s11 + DT * (inv_mass * Fz + s12);
    w13[12] = s12;
    __syncthreads();

    if (fullBlock) {
        float4* dst = (float4*)(out + (size_t)blockBase * ROW);
        const float4* src = (const float4*)sout;
        #pragma unroll
        for (int j = 0; j < 4; j++) {
            int idx = tid + j * NTHREADS;
            if (idx < BLK_VEC4) dst[idx] = src[idx];
        }
    } else {
        int lim = (n - blockBase) * ROW;
        float* dst = out + (size_t)blockBase * ROW;
        for (int j = tid; j < lim; j += NTHREADS) dst[j] = sout[j];
    }
}

extern "C" void kernel_launch(void* const* d_in, const int* in_sizes, int n_in,
                              void* d_out, int out_size) {
    const float* params   = (const float*)d_in[0];
    const float* states   = (const float*)d_in[1];
    const float* actions  = (const float*)d_in[2];
    const float* foot_pos = (const float*)d_in[3];
    const int*   foot_contacts = (const int*)d_in[4];
    float* out = (float*)d_out;

    int n = in_sizes[1] / 13;
    int blocks = (n + NTHREADS - 1) / NTHREADS;
    get_next_states_kernel<<<blocks, NTHREADS>>>(params, states, actions,
                                                 foot_pos, foot_contacts, out, n);
}

// round 6
// speedup vs baseline: 1.9152x; 1.1667x over previous
#include <cuda_runtime.h>

#define DT 0.025f
#define NTHREADS 128
#define ROW 13
#define BLK_FLOATS (NTHREADS * ROW)          // 1664
#define BLK_VEC4   (BLK_FLOATS / 4)          // 416

__global__ void __launch_bounds__(NTHREADS, 8)
get_next_states_kernel(const float* __restrict__ params,
                       const float* __restrict__ states,
                       const float* __restrict__ actions,
                       const float* __restrict__ foot_pos,
                       const int* __restrict__ foot_contacts,
                       float* __restrict__ out,
                       int n)
{
    __shared__ float sin_[BLK_FLOATS];
    __shared__ float sout[BLK_FLOATS];

    int tid = threadIdx.x;
    int blockBase = blockIdx.x * NTHREADS;
    int i = blockBase + tid;
    bool fullBlock = (blockBase + NTHREADS) <= n;

    // ---- per-kernel constants from params (broadcast L1 hits) ----
    float p0 = __ldg(params + 0);
    float p1 = __ldg(params + 1);
    float p2 = __ldg(params + 2);
    float p3 = __ldg(params + 3);
    float p4 = __ldg(params + 4);
    float p5 = __ldg(params + 5);
    float p6 = __ldg(params + 6);

    // ---- issue independent per-row loads early (overlap with staging) ----
    float4 aA, aB, aC, fA, fB, fC;
    int4 fc4 = make_int4(0, 0, 0, 0);
    if (i < n) {
        const float4* a4 = (const float4*)(actions  + (size_t)i * 12);
        const float4* f4 = (const float4*)(foot_pos + (size_t)i * 12);
        aA = a4[0]; aB = a4[1]; aC = a4[2];
        fA = f4[0]; fB = f4[1]; fC = f4[2];
        fc4 = *(const int4*)(foot_contacts + (size_t)i * 4);
    } else {
        aA = aB = aC = fA = fB = fC = make_float4(0.f, 0.f, 0.f, 0.f);
    }

    // ---- cooperative coalesced stage of states into smem ----
    if (fullBlock) {
        const float4* src = (const float4*)(states + (size_t)blockBase * ROW);
        float4* dst = (float4*)sin_;
        #pragma unroll
        for (int j = 0; j < 4; j++) {
            int idx = tid + j * NTHREADS;
            if (idx < BLK_VEC4) dst[idx] = src[idx];
        }
    } else {
        int lim = (n - blockBase) * ROW;
        const float* src = states + (size_t)blockBase * ROW;
        for (int j = tid; j < lim; j += NTHREADS) sin_[j] = src[j];
    }
    __syncthreads();

    // ---- per-row state reads from smem (stride 13: bank-conflict-free) ----
    const float* s = sin_ + tid * ROW;
    float s0 = s[0],  s1 = s[1],  s2 = s[2],  s3 = s[3],  s4 = s[4];
    float s5 = s[5],  s6 = s[6],  s7 = s[7],  s8 = s[8],  s9 = s[9];
    float s10 = s[10], s11 = s[11], s12 = s[12];

    // ---- constants: inertia inverse (recomputed per thread, ALU-cheap) ----
    float inv_mass = 1.0f / p0;
    float I00 = p1*p1 + 1e-5f;
    float I01 = p1*p2 + 1e-5f;
    float I02 = p1*p4 + 1e-5f;
    float I11 = p2*p2 + p3*p3 + 1e-5f;
    float I12 = p2*p4 + p3*p5 + 1e-5f;
    float I22 = p4*p4 + p5*p5 + p6*p6 + 1e-5f;
    float c00 = I11*I22 - I12*I12;
    float c01 = I02*I12 - I01*I22;
    float c02 = I01*I12 - I02*I11;
    float det = I00*c00 + I01*c01 + I02*c02;
    float invdet = 1.0f / det;
    float iI00 = c00 * invdet;
    float iI01 = c01 * invdet;
    float iI02 = c02 * invdet;
    float iI11 = (I00*I22 - I02*I02) * invdet;
    float iI12 = (I02*I01 - I00*I12) * invdet;
    float iI22 = (I00*I11 - I01*I01) * invdet;

    // Hybrid precision trig:
    //  - pitch uses PRECISE sincosf (cp feeds 1/cp and tan — MUFU error there
    //    is amplified ~1000x for |pitch| near pi/2, which is what failed R5)
    //  - roll/yaw sin/cos are only ever multiplied, MUFU error (~3e-7)
    //    propagates un-amplified -> safe with fast path
    float sr, cr, sp, cp, sy, cy;
    __sincosf(s0, &sr, &cr);
    sincosf(s1, &sp, &cp);
    __sincosf(s2, &sy, &cy);

    float R00 = cy*cp, R01 = cy*sp*sr - sy*cr, R02 = cy*sp*cr + sy*sr;
    float R10 = sy*cp, R11 = sy*sp*sr + cy*cr, R12 = sy*sp*cr - cy*sr;
    float R20 = -sp,   R21 = cp*sr,            R22 = cp*cr;
    float rcp_cp = 1.0f / cp;

    float ax[4] = { aA.x, aA.w, aB.z, aC.y };
    float ay[4] = { aA.y, aB.x, aB.w, aC.z };
    float az[4] = { aA.z, aB.y, aC.x, aC.w };
    float px[4] = { fA.x, fA.w, fB.z, fC.y };
    float py[4] = { fA.y, fB.x, fB.w, fC.z };
    float pz[4] = { fA.z, fB.y, fC.x, fC.w };
    float fcw[4] = { (float)(fc4.x != 0), (float)(fc4.y != 0),
                     (float)(fc4.z != 0), (float)(fc4.w != 0) };

    // w = sum_f fc * (foot_world_f x a_f); F = sum_f fc * a_f
    float wx = 0.f, wy = 0.f, wz = 0.f;
    float Fx = 0.f, Fy = 0.f, Fz = 0.f;
    #pragma unroll
    for (int f = 0; f < 4; f++) {
        float vx = R00*px[f] + R01*py[f] + R02*pz[f];
        float vy = R10*px[f] + R11*py[f] + R12*pz[f];
        float vz = R20*px[f] + R21*py[f] + R22*pz[f];
        wx += fcw[f] * (vy*az[f] - vz*ay[f]);
        wy += fcw[f] * (vz*ax[f] - vx*az[f]);
        wz += fcw[f] * (vx*ay[f] - vy*ax[f]);
        Fx += fcw[f] * ax[f];
        Fy += fcw[f] * ay[f];
        Fz += fcw[f] * az[f];
    }

    // t = R * invI * R^T * w
    float ux = R00*wx + R10*wy + R20*wz;
    float uy = R01*wx + R11*wy + R21*wz;
    float uz = R02*wx + R12*wy + R22*wz;
    float vx = iI00*ux + iI01*uy + iI02*uz;
    float vy = iI01*ux + iI11*uy + iI12*uz;
    float vz = iI02*ux + iI12*uy + iI22*uz;
    float tx = R00*vx + R01*vy + R02*vz;
    float ty = R10*vx + R11*vy + R12*vz;
    float tz = R20*vx + R21*vy + R22*vz;

    float m0 = cy*s6 + sy*s7;

    // ---- write results to the separate output staging buffer ----
    float* w13 = sout + tid * ROW;
    w13[0]  = s0 + DT * (m0 * rcp_cp);
    w13[1]  = s1 + DT * (cy*s7 - sy*s6);
    w13[2]  = s2 + DT * (m0 * sp * rcp_cp + s8);
    w13[3]  = s3 + DT * s9;
    w13[4]  = s4 + DT * s10;
    w13[5]  = s5 + DT * s11;
    w13[6]  = s6 + DT * tx;
    w13[7]  = s7 + DT * ty;
    w13[8]  = s8 + DT * tz;
    w13[9]  = s9  + DT * inv_mass * Fx;
    w13[10] = s10 + DT * inv_mass * Fy;
    w13[11] = s11 + DT * (inv_mass * Fz + s12);
    w13[12] = s12;
    __syncthreads();

    if (fullBlock) {
        float4* dst = (float4*)(out + (size_t)blockBase * ROW);
        const float4* src = (const float4*)sout;
        #pragma unroll
        for (int j = 0; j < 4; j++) {
            int idx = tid + j * NTHREADS;
            if (idx < BLK_VEC4) dst[idx] = src[idx];
        }
    } else {
        int lim = (n - blockBase) * ROW;
        float* dst = out + (size_t)blockBase * ROW;
        for (int j = tid; j < lim; j += NTHREADS) dst[j] = sout[j];
    }
}

extern "C" void kernel_launch(void* const* d_in, const int* in_sizes, int n_in,
                              void* d_out, int out_size) {
    const float* params   = (const float*)d_in[0];
    const float* states   = (const float*)d_in[1];
    const float* actions  = (const float*)d_in[2];
    const float* foot_pos = (const float*)d_in[3];
    const int*   foot_contacts = (const int*)d_in[4];
    float* out = (float*)d_out;

    int n = in_sizes[1] / 13;
    int blocks = (n + NTHREADS - 1) / NTHREADS;
    get_next_states_kernel<<<blocks, NTHREADS>>>(params, states, actions,
                                                 foot_pos, foot_contacts, out, n);
}